// round 7
// baseline (speedup 1.0000x reference)
#include <cuda_runtime.h>

// QCNN_58025008169535: 4-qubit quantum circuit sim per 2x2 image patch.
// x: [32,128,128,3] f32, w: [4,4,3] f32 -> out: [32, 127*127, 4] f32.
//
// Packed f32x2 (FFMA2) implementation. State stored as 8 ull (lane0 = amp k,
// lane1 = amp k+8, k = i&7). Gates on q1..q3 are lane-parallel with
// broadcast coefficient packs; the q0 gate uses a lane swap with per-lane
// packs A=(u00,u11), B=(u01,u10). CZ masks = 64-bit sign XORs.
// Earlier algebra retained: encoding-Rz drop, gate fusion, layer-0
// product-state fold, final-layer Rz/CZ drop, sign-tree measurement.

#define NQ 4
#define NL 4

typedef unsigned long long ull;

constexpr int BATCH = 32;
constexpr int Hh = 128, Ww = 128, Cc = 3;
constexpr int PH = 127, PW = 127;
constexpr int PP = PH * PW;

__device__ float gU0[NQ * 8];        // layer-0 fused gates (scalar)
__device__ ull  gUP[3 * NQ * 12];    // layers 1..3 packed coefficient sets

// ---------- f32x2 helpers ----------
__device__ __forceinline__ ull f2pk(float lo, float hi) {
    ull r; asm("mov.b64 %0, {%1, %2};" : "=l"(r) : "f"(lo), "f"(hi)); return r;
}
__device__ __forceinline__ void f2up(ull v, float& lo, float& hi) {
    asm("mov.b64 {%0, %1}, %2;" : "=f"(lo), "=f"(hi) : "l"(v));
}
__device__ __forceinline__ ull f2swap(ull v) {
    float lo, hi; f2up(v, lo, hi); return f2pk(hi, lo);
}
__device__ __forceinline__ ull ffma2(ull a, ull b, ull c) {
    ull d; asm("fma.rn.f32x2 %0, %1, %2, %3;" : "=l"(d) : "l"(a), "l"(b), "l"(c)); return d;
}
__device__ __forceinline__ ull fmul2(ull a, ull b) {
    ull d; asm("mul.rn.f32x2 %0, %1, %2;" : "=l"(d) : "l"(a), "l"(b)); return d;
}

__global__ __launch_bounds__(32)
void precompute_gates(const float* __restrict__ w) {
    int t = threadIdx.x;
    if (t >= NL * NQ) return;
    int layer = t >> 2, q = t & 3;
    float a = w[t * 3 + 0], b = w[t * 3 + 1], g = w[t * 3 + 2];
    float ca, sa, cb, sb, cg, sg;
    sincosf(0.5f * a, &sa, &ca);
    sincosf(0.5f * b, &sb, &cb);
    if (layer == NL - 1) { cg = 1.0f; sg = 0.0f; }   // final Rz invisible to |psi|^2
    else                 { sincosf(0.5f * g, &sg, &cg); }
    // M = Ry(b)*Rx(a); U = Rz(g)*M
    float M00r =  cb * ca, M00i =  sb * sa;
    float M01r = -sb * ca, M01i = -cb * sa;
    float M10r =  sb * ca, M10i = -cb * sa;
    float M11r =  cb * ca, M11i = -sb * sa;
    float u00r = cg * M00r + sg * M00i, u00i = cg * M00i - sg * M00r;
    float u01r = cg * M01r + sg * M01i, u01i = cg * M01i - sg * M01r;
    float u10r = cg * M10r - sg * M10i, u10i = cg * M10i + sg * M10r;
    float u11r = cg * M11r - sg * M11i, u11i = cg * M11i + sg * M11r;

    if (layer == 0) {
        float* o = &gU0[q * 8];
        o[0] = u00r; o[1] = u00i; o[2] = u01r; o[3] = u01i;
        o[4] = u10r; o[5] = u10i; o[6] = u11r; o[7] = u11i;
    } else {
        ull* o = &gUP[((layer - 1) * NQ + q) * 12];
        if (q == 0) {   // swap-form packs: A=(u00,u11), B=(u01,u10)
            o[0] = f2pk(u00r,  u11r); o[1] = f2pk(u00i,  u11i); o[2] = f2pk(-u00i, -u11i);
            o[3] = f2pk(u01r,  u10r); o[4] = f2pk(u01i,  u10i); o[5] = f2pk(-u01i, -u10i);
            o[6] = 0; o[7] = 0; o[8] = 0; o[9] = 0; o[10] = 0; o[11] = 0;
        } else {        // broadcast packs
            o[0] = f2pk(u00r, u00r); o[1]  = f2pk(u00i, u00i); o[2]  = f2pk(-u00i, -u00i);
            o[3] = f2pk(u01r, u01r); o[4]  = f2pk(u01i, u01i); o[5]  = f2pk(-u01i, -u01i);
            o[6] = f2pk(u10r, u10r); o[7]  = f2pk(u10i, u10i); o[8]  = f2pk(-u10i, -u10i);
            o[9] = f2pk(u11r, u11r); o[10] = f2pk(u11i, u11i); o[11] = f2pk(-u11i, -u11i);
        }
    }
}

__global__ __launch_bounds__(256)
void qcnn_kernel(const float* __restrict__ x, float* __restrict__ out) {
    __shared__ float sG[NQ * 8];
    __shared__ ull  sP[3 * NQ * 12];
    if (threadIdx.x < NQ * 8) sG[threadIdx.x] = gU0[threadIdx.x];
    if (threadIdx.x < 3 * NQ * 12) sP[threadIdx.x] = gUP[threadIdx.x];
    __syncthreads();

    int p = blockIdx.x * blockDim.x + threadIdx.x;
    if (p >= PP) return;
    int b = blockIdx.y;
    int r = p / PW;
    int c = p - r * PW;
    const float* px = x + ((size_t)(b * Hh + r) * Ww + c) * Cc;

    const float PI = 3.14159265358979f;

    // Encoding (global phase dropped) + layer-0 gate on per-qubit 2-vectors.
    float vr[NQ][2], vi[NQ][2];
#pragma unroll
    for (int n = 0; n < NQ; n++) {
        const float* pp = px + (((n >> 1) * Ww) + (n & 1)) * Cc;
        float c1 = pp[1], c2 = pp[2];
        float st, ct, sp, cp;
        __sincosf(0.5f * PI * c1, &st, &ct);
        __sincosf(PI * c2, &sp, &cp);
        float v0r = ct,      v0i = 0.0f;
        float v1r = st * cp, v1i = st * sp;
        const float* u = &sG[n * 8];
        float u00r = u[0], u00i = u[1], u01r = u[2], u01i = u[3];
        float u10r = u[4], u10i = u[5], u11r = u[6], u11i = u[7];
        vr[n][0] = u00r * v0r - u00i * v0i + u01r * v1r - u01i * v1i;
        vi[n][0] = u00r * v0i + u00i * v0r + u01r * v1i + u01i * v1r;
        vr[n][1] = u10r * v0r - u10i * v0i + u11r * v1r - u11i * v1i;
        vi[n][1] = u10r * v0i + u10i * v0r + u11r * v1i + u11i * v1r;
    }

    // Outer products: (q0,q1) -> ar/ai, (q2,q3) -> brv/biv.
    float ar[4], ai[4], brv[4], biv[4];
#pragma unroll
    for (int i = 0; i < 4; i++) {
        int b0 = i >> 1, b1 = i & 1;
        ar[i]  = vr[0][b0] * vr[1][b1] - vi[0][b0] * vi[1][b1];
        ai[i]  = vr[0][b0] * vi[1][b1] + vi[0][b0] * vr[1][b1];
        brv[i] = vr[2][b0] * vr[3][b1] - vi[2][b0] * vi[3][b1];
        biv[i] = vr[2][b0] * vi[3][b1] + vi[2][b0] * vr[3][b1];
    }

    // Packed state: lane0 = amp k (b0=0), lane1 = amp k+8 (b0=1), k = b1b2b3.
    ull Pre[8], Pim[8];
    {
        ull Par0 = f2pk(ar[0], ar[2]), Par1 = f2pk(ar[1], ar[3]);
        ull Pai0 = f2pk(ai[0], ai[2]), Pai1 = f2pk(ai[1], ai[3]);
        ull Bre[4], Bim[4], nBim[4];
#pragma unroll
        for (int lo = 0; lo < 4; lo++) {
            Bre[lo]  = f2pk(brv[lo],  brv[lo]);
            Bim[lo]  = f2pk(biv[lo],  biv[lo]);
            nBim[lo] = f2pk(-biv[lo], -biv[lo]);
        }
#pragma unroll
        for (int k = 0; k < 8; k++) {
            int lo = k & 3;
            ull Ar = (k >> 2) ? Par1 : Par0;
            ull Ai = (k >> 2) ? Pai1 : Pai0;
            Pre[k] = ffma2(Ar, Bre[lo], fmul2(Ai, nBim[lo]));
            Pim[k] = ffma2(Ar, Bim[lo], fmul2(Ai, Bre[lo]));
        }
    }

    // CZ sign mask in packed form (from sign = (-1)^(b0b1 ^ b2b3 ^ b1b2),
    // flips at i in {3,6,11,12,13,15}):
    //   k=3: both lanes; k=4,5,7: lane1; k=6: lane0.
    const ull SBOTH = 0x8000000080000000ULL;
    const ull SHI   = 0x8000000000000000ULL;
    const ull SLO   = 0x0000000080000000ULL;
#define CZ_MASK() do { \
        Pre[3] ^= SBOTH; Pim[3] ^= SBOTH; \
        Pre[4] ^= SHI;   Pim[4] ^= SHI;   \
        Pre[5] ^= SHI;   Pim[5] ^= SHI;   \
        Pre[6] ^= SLO;   Pim[6] ^= SLO;   \
        Pre[7] ^= SHI;   Pim[7] ^= SHI;   \
    } while (0)

    CZ_MASK();   // layer-0 CZs (gates already folded into product state)

#pragma unroll
    for (int h = 1; h < NL; h++) {
        const ull* gp = &sP[(h - 1) * NQ * 12];
        // q0: lanes mixed via swap; packs A=(u00,u11), B=(u01,u10).
        {
            ull Ar = gp[0], Ai = gp[1], nAi = gp[2];
            ull Br = gp[3], Bi = gp[4], nBi = gp[5];
#pragma unroll
            for (int k = 0; k < 8; k++) {
                ull xr = Pre[k], xi = Pim[k];
                ull sr = f2swap(xr), si = f2swap(xi);
                Pre[k] = ffma2(Ar, xr, ffma2(nAi, xi, ffma2(Br, sr, fmul2(nBi, si))));
                Pim[k] = ffma2(Ar, xi, ffma2(Ai, xr, ffma2(Br, si, fmul2(Bi, sr))));
            }
        }
        // q1..q3: lane-parallel butterflies, k-space strides 4,2,1.
#pragma unroll
        for (int q = 1; q < NQ; q++) {
            const ull* u = &gp[q * 12];
            ull c00r = u[0], c00i = u[1], n00i = u[2];
            ull c01r = u[3], c01i = u[4], n01i = u[5];
            ull c10r = u[6], c10i = u[7], n10i = u[8];
            ull c11r = u[9], c11i = u[10], n11i = u[11];
            int s = 8 >> q;
#pragma unroll
            for (int k = 0; k < 8; k++) {
                if (k & s) continue;
                int j = k | s;
                ull xr = Pre[k], xi = Pim[k], yr = Pre[j], yi = Pim[j];
                Pre[k] = ffma2(c00r, xr, ffma2(n00i, xi, ffma2(c01r, yr, fmul2(n01i, yi))));
                Pim[k] = ffma2(c00r, xi, ffma2(c00i, xr, ffma2(c01r, yi, fmul2(c01i, yr))));
                Pre[j] = ffma2(c10r, xr, ffma2(n10i, xi, ffma2(c11r, yr, fmul2(n11i, yi))));
                Pim[j] = ffma2(c10r, xi, ffma2(c10i, xr, ffma2(c11r, yi, fmul2(c11i, yr))));
            }
        }
        if (h < NL - 1) CZ_MASK();   // final layer's CZs invisible to |psi|^2
    }

    // Probabilities (packed squares), then scalar sign tree.
    float pr[16];
#pragma unroll
    for (int k = 0; k < 8; k++) {
        ull p2 = ffma2(Pre[k], Pre[k], fmul2(Pim[k], Pim[k]));
        f2up(p2, pr[k], pr[k + 8]);
    }

    float s8[8], z3 = 0.f;
#pragma unroll
    for (int k = 0; k < 8; k++) {
        s8[k] = pr[2 * k] + pr[2 * k + 1];
        z3 += pr[2 * k] - pr[2 * k + 1];
    }
    float s4[4], z2 = 0.f;
#pragma unroll
    for (int k = 0; k < 4; k++) {
        s4[k] = s8[2 * k] + s8[2 * k + 1];
        z2 += s8[2 * k] - s8[2 * k + 1];
    }
    float z1 = (s4[0] - s4[1]) + (s4[2] - s4[3]);
    float z0 = (s4[0] + s4[1]) - (s4[2] + s4[3]);

    float4 o;
    o.x = z0; o.y = z1; o.z = z2; o.w = z3;
    reinterpret_cast<float4*>(out)[(size_t)b * PP + p] = o;
}

extern "C" void kernel_launch(void* const* d_in, const int* in_sizes, int n_in,
                              void* d_out, int out_size) {
    const float* x = (const float*)d_in[0];
    const float* w = (const float*)d_in[1];
    if (n_in >= 2 && in_sizes[0] < in_sizes[1]) {
        x = (const float*)d_in[1];
        w = (const float*)d_in[0];
    }
    precompute_gates<<<1, 32>>>(w);
    dim3 grid((PP + 255) / 256, BATCH);
    qcnn_kernel<<<grid, 256>>>(x, (float*)d_out);
}